// round 2
// baseline (speedup 1.0000x reference)
#include <cuda_runtime.h>
#include <cstdint>
#include <cstddef>

#define NPTS 10000
#define NF   128
#define NH   64
#define KNN  16
#define KSPLIT 5
#define KCHUNK 2000   // 5 * 2000 = 10000

// ---------------- scratch (device globals: allocation-free) ----------------
static __device__ float g_dist[(size_t)NPTS * NPTS];        // 400 MB
static __device__ int   g_knn [NPTS * KNN];
static __device__ float g_sq  [NPTS];
static __device__ float g_pa  [NPTS * NF];
static __device__ float g_pb  [NPTS * NF];
static __device__ float g_qa  [NPTS * NF];
static __device__ float g_qb  [NPTS * NF];
static __device__ float g_part[KSPLIT][NPTS * NF];
static __device__ float g_z   [NPTS * NF];                  // [z1 | z2]
static __device__ float g_res [NPTS * NF];

// ---------------- row squared norms ----------------
__global__ void rownorm_k(const float* __restrict__ x) {
    __shared__ float s[NF];
    const int r = blockIdx.x, t = threadIdx.x;
    float v = x[(size_t)r * NF + t];
    s[t] = v * v;
    __syncthreads();
    for (int o = NF / 2; o > 0; o >>= 1) {
        if (t < o) s[t] += s[t + o];
        __syncthreads();
    }
    if (t == 0) g_sq[r] = s[0];
}

// ---------------- C = A @ B^T  (K = 128), 128x128 tile, 256 threads -------
// mode 0: dist epilogue  (sq[m] + sq[n] - 2c, +1e30 on diag) -> C
// mode 1: plain store -> C
__global__ void __launch_bounds__(256) gemm_nt_k(const float* __restrict__ A,
                                                 const float* __restrict__ B,
                                                 float* __restrict__ C,
                                                 int mode) {
    __shared__ float As[8][132];
    __shared__ float Bs[8][132];
    const int bm = blockIdx.y * 128, bn = blockIdx.x * 128;
    const int tid = threadIdx.x;
    const int tx = tid & 15, ty = tid >> 4;
    const int lr = tid >> 1, lk = (tid & 1) * 4;

    float acc[8][8];
#pragma unroll
    for (int i = 0; i < 8; i++)
#pragma unroll
        for (int j = 0; j < 8; j++) acc[i][j] = 0.f;

    for (int k0 = 0; k0 < NF; k0 += 8) {
        float4 av = make_float4(0.f, 0.f, 0.f, 0.f);
        float4 bv = make_float4(0.f, 0.f, 0.f, 0.f);
        if (bm + lr < NPTS) av = *(const float4*)(A + (size_t)(bm + lr) * NF + k0 + lk);
        if (bn + lr < NPTS) bv = *(const float4*)(B + (size_t)(bn + lr) * NF + k0 + lk);
        __syncthreads();
        As[lk + 0][lr] = av.x; As[lk + 1][lr] = av.y;
        As[lk + 2][lr] = av.z; As[lk + 3][lr] = av.w;
        Bs[lk + 0][lr] = bv.x; Bs[lk + 1][lr] = bv.y;
        Bs[lk + 2][lr] = bv.z; Bs[lk + 3][lr] = bv.w;
        __syncthreads();
#pragma unroll
        for (int kk = 0; kk < 8; kk++) {
            float4 a0 = *(const float4*)(&As[kk][ty * 8]);
            float4 a1 = *(const float4*)(&As[kk][ty * 8 + 4]);
            float4 b0 = *(const float4*)(&Bs[kk][tx * 8]);
            float4 b1 = *(const float4*)(&Bs[kk][tx * 8 + 4]);
            float a[8] = {a0.x, a0.y, a0.z, a0.w, a1.x, a1.y, a1.z, a1.w};
            float b[8] = {b0.x, b0.y, b0.z, b0.w, b1.x, b1.y, b1.z, b1.w};
#pragma unroll
            for (int i = 0; i < 8; i++)
#pragma unroll
                for (int j = 0; j < 8; j++) acc[i][j] = fmaf(a[i], b[j], acc[i][j]);
        }
    }

    float sqn[8];
    if (mode == 0) {
#pragma unroll
        for (int j = 0; j < 8; j++) {
            const int n = bn + tx * 8 + j;
            sqn[j] = (n < NPTS) ? g_sq[n] : 0.f;
        }
    }

#pragma unroll
    for (int i = 0; i < 8; i++) {
        const int m = bm + ty * 8 + i;
        if (m >= NPTS) continue;
        const float sm = (mode == 0) ? g_sq[m] : 0.f;
#pragma unroll
        for (int j = 0; j < 8; j++) {
            const int n = bn + tx * 8 + j;
            if (n >= NPTS) continue;
            float c = acc[i][j];
            if (mode == 0) {
                c = sm + sqn[j] - 2.f * c;
                if (m == n) c += 1e30f;
            }
            C[(size_t)m * NPTS + n] = c;
        }
    }
}

// ---------------- top-16 per row (lexicographic: (dist, idx) min) ---------
__global__ void __launch_bounds__(256) topk_k() {
    __shared__ float sv[4096];
    __shared__ int   si[4096];
    __shared__ float rv[256];
    __shared__ int   ri[256];
    __shared__ int   rp[256];
    const int r = blockIdx.x, t = threadIdx.x;
    const float* drow = g_dist + (size_t)r * NPTS;

    float lv[KNN]; int li[KNN];
#pragma unroll
    for (int i = 0; i < KNN; i++) { lv[i] = 3.4e38f; li[i] = 0x7fffffff; }
    float wv = 3.4e38f; int wi = 0x7fffffff, wp = 0;

    for (int j = t; j < NPTS; j += 256) {
        const float v = drow[j];
        if (v < wv || (v == wv && j < wi)) {
            lv[wp] = v; li[wp] = j;
            wv = -3.4e38f; wi = -1;
#pragma unroll
            for (int i = 0; i < KNN; i++) {
                if (lv[i] > wv || (lv[i] == wv && li[i] > wi)) {
                    wv = lv[i]; wi = li[i]; wp = i;
                }
            }
        }
    }
#pragma unroll
    for (int i = 0; i < KNN; i++) { sv[t * KNN + i] = lv[i]; si[t * KNN + i] = li[i]; }
    __syncthreads();

    for (int sel = 0; sel < KNN; sel++) {
        float bv = 3.5e38f; int bi = 0x7fffffff, bp = -1;
        for (int q = t; q < 4096; q += 256) {
            const float v = sv[q]; const int ii = si[q];
            if (v < bv || (v == bv && ii < bi)) { bv = v; bi = ii; bp = q; }
        }
        rv[t] = bv; ri[t] = bi; rp[t] = bp;
        __syncthreads();
        for (int o = 128; o > 0; o >>= 1) {
            if (t < o) {
                if (rv[t + o] < rv[t] || (rv[t + o] == rv[t] && ri[t + o] < ri[t])) {
                    rv[t] = rv[t + o]; ri[t] = ri[t + o]; rp[t] = rp[t + o];
                }
            }
            __syncthreads();
        }
        if (t == 0) {
            g_knn[r * KNN + sel] = ri[0];
            sv[rp[0]] = 3.5e38f; si[rp[0]] = 0x7fffffff;
        }
        __syncthreads();
    }
}

// ---------------- dense hop: partial[chunk] = adj[:, chunk] @ Hin[chunk] --
// 64x128 tile, K chunk of 2000 per block, grid (157, KSPLIT)
__global__ void __launch_bounds__(256) hop_gemm_k(const float* __restrict__ adj,
                                                  const float* __restrict__ Hin) {
    __shared__ float As[16][66];
    __shared__ float Bs[16][128];
    const int bm = blockIdx.x * 64;
    const int chunk = blockIdx.y;
    const int tid = threadIdx.x;
    const int tx = tid & 15, ty = tid >> 4;
    const int arow = tid >> 2, ak = (tid & 3) * 4;
    const int brow = tid >> 5, bcol = (tid & 31) * 4;
    const bool mok = (bm + arow) < NPTS;
    const float* ap = adj + (size_t)(bm + arow) * NPTS;

    float acc[4][8];
#pragma unroll
    for (int i = 0; i < 4; i++)
#pragma unroll
        for (int j = 0; j < 8; j++) acc[i][j] = 0.f;

    const int kbase = chunk * KCHUNK;
    for (int kt = 0; kt < KCHUNK; kt += 16) {
        const int k0 = kbase + kt;
        float4 av = make_float4(0.f, 0.f, 0.f, 0.f);
        if (mok) av = *(const float4*)(ap + k0 + ak);
        const float4 bv0 = *(const float4*)(Hin + (size_t)(k0 + brow) * NF + bcol);
        const float4 bv1 = *(const float4*)(Hin + (size_t)(k0 + brow + 8) * NF + bcol);
        __syncthreads();
        As[ak + 0][arow] = av.x; As[ak + 1][arow] = av.y;
        As[ak + 2][arow] = av.z; As[ak + 3][arow] = av.w;
        *(float4*)(&Bs[brow][bcol]) = bv0;
        *(float4*)(&Bs[brow + 8][bcol]) = bv1;
        __syncthreads();
#pragma unroll
        for (int kk = 0; kk < 16; kk++) {
            const float a0 = As[kk][ty * 4 + 0];
            const float a1 = As[kk][ty * 4 + 1];
            const float a2 = As[kk][ty * 4 + 2];
            const float a3 = As[kk][ty * 4 + 3];
            const float4 b0 = *(const float4*)(&Bs[kk][tx * 8]);
            const float4 b1 = *(const float4*)(&Bs[kk][tx * 8 + 4]);
            const float b[8] = {b0.x, b0.y, b0.z, b0.w, b1.x, b1.y, b1.z, b1.w};
            const float a[4] = {a0, a1, a2, a3};
#pragma unroll
            for (int i = 0; i < 4; i++)
#pragma unroll
                for (int j = 0; j < 8; j++) acc[i][j] = fmaf(a[i], b[j], acc[i][j]);
        }
    }

    float* outp = g_part[chunk];
#pragma unroll
    for (int i = 0; i < 4; i++) {
        const int m = bm + ty * 4 + i;
        if (m < NPTS) {
            float4 o0 = make_float4(acc[i][0], acc[i][1], acc[i][2], acc[i][3]);
            float4 o1 = make_float4(acc[i][4], acc[i][5], acc[i][6], acc[i][7]);
            *(float4*)(outp + (size_t)m * NF + tx * 8)     = o0;
            *(float4*)(outp + (size_t)m * NF + tx * 8 + 4) = o1;
        }
    }
}

// out = 0.5 * (sum of KSPLIT partials) + 0.5 * x
__global__ void combine_k(const float* __restrict__ x, float* __restrict__ out) {
    const int i = blockIdx.x * 256 + threadIdx.x;
    if (i < NPTS * NF) {
        float s = g_part[0][i] + g_part[1][i] + g_part[2][i] + g_part[3][i] + g_part[4][i];
        out[i] = 0.5f * s + 0.5f * x[i];
    }
}

// ---------------- sparse knn hop: out = 0.5*(1/16)*sum(nb) + 0.5*x --------
__global__ void sparse_hop_k(const float* __restrict__ Hin,
                             const float* __restrict__ x,
                             float* __restrict__ Hout) {
    __shared__ int nb[KNN];
    const int r = blockIdx.x, t = threadIdx.x;   // 128 threads
    if (t < KNN) nb[t] = g_knn[r * KNN + t];
    __syncthreads();
    float s = 0.f;
#pragma unroll
    for (int i = 0; i < KNN; i++) s += Hin[(size_t)nb[i] * NF + t];
    Hout[(size_t)r * NF + t] = 0.03125f * s + 0.5f * x[(size_t)r * NF + t];
}

// ---------------- small dense layers: out = [relu](In @ W + b) ------------
__global__ void linear_k(const float* __restrict__ In, int ldin,
                         const float* __restrict__ W, const float* __restrict__ b,
                         float* __restrict__ Out, int ldout, int coff,
                         int Kdim, int Ndim, int dorelu) {
    extern __shared__ float rs[];
    const int r = blockIdx.x, t = threadIdx.x;   // Ndim threads
    for (int k = t; k < Kdim; k += blockDim.x) rs[k] = In[(size_t)r * ldin + k];
    __syncthreads();
    float acc = b[t];
    for (int k = 0; k < Kdim; k++) acc = fmaf(rs[k], W[k * Ndim + t], acc);
    if (dorelu) acc = fmaxf(acc, 0.f);
    Out[(size_t)r * ldout + coff + t] = acc;
}

// ---------------- launch ---------------------------------------------------
extern "C" void kernel_launch(void* const* d_in, const int* in_sizes, int n_in,
                              void* d_out, int out_size) {
    (void)in_sizes; (void)n_in; (void)out_size;
    const float* x      = (const float*)d_in[0];
    const float* adj    = (const float*)d_in[1];
    const float* W_enc  = (const float*)d_in[2];
    const float* b_enc  = (const float*)d_in[3];
    const float* W_enc2 = (const float*)d_in[4];
    const float* b_enc2 = (const float*)d_in[5];
    const float* W_dec  = (const float*)d_in[6];
    const float* b_dec  = (const float*)d_in[7];

    float* out    = (float*)d_out;
    float* out_h1 = out;
    float* out_h2 = out + (size_t)NPTS * NH;
    float* out_G  = out + (size_t)2 * NPTS * NH;

    float *pa, *pb, *qa, *qb, *z, *res, *dist;
    cudaGetSymbolAddress((void**)&pa,   g_pa);
    cudaGetSymbolAddress((void**)&pb,   g_pb);
    cudaGetSymbolAddress((void**)&qa,   g_qa);
    cudaGetSymbolAddress((void**)&qb,   g_qb);
    cudaGetSymbolAddress((void**)&z,    g_z);
    cudaGetSymbolAddress((void**)&res,  g_res);
    cudaGetSymbolAddress((void**)&dist, g_dist);

    const dim3 gNT((NPTS + 127) / 128, (NPTS + 127) / 128);
    const dim3 gHop((NPTS + 63) / 64, KSPLIT);
    const int  gComb = (NPTS * NF + 255) / 256;

    // 1. distances + knn
    rownorm_k<<<NPTS, NF>>>(x);
    gemm_nt_k<<<gNT, 256>>>(x, x, dist, 0);
    topk_k<<<NPTS, 256>>>();

    // 2. sparse (knn) propagation, 5 hops: x->qa->qb->qa->qb->qa
    sparse_hop_k<<<NPTS, NF>>>(x,  x, qa);
    sparse_hop_k<<<NPTS, NF>>>(qa, x, qb);
    sparse_hop_k<<<NPTS, NF>>>(qb, x, qa);
    sparse_hop_k<<<NPTS, NF>>>(qa, x, qb);
    sparse_hop_k<<<NPTS, NF>>>(qb, x, qa);

    // 3. dense (adj) propagation, 5 hops: x->pa->pb->pa->pb->pa
    hop_gemm_k<<<gHop, 256>>>(adj, x);   combine_k<<<gComb, 256>>>(x, pa);
    hop_gemm_k<<<gHop, 256>>>(adj, pa);  combine_k<<<gComb, 256>>>(x, pb);
    hop_gemm_k<<<gHop, 256>>>(adj, pb);  combine_k<<<gComb, 256>>>(x, pa);
    hop_gemm_k<<<gHop, 256>>>(adj, pa);  combine_k<<<gComb, 256>>>(x, pb);
    hop_gemm_k<<<gHop, 256>>>(adj, pb);  combine_k<<<gComb, 256>>>(x, pa);

    // 4. encoders -> outputs h1, h2
    linear_k<<<NPTS, NH, NF * 4>>>(pa, NF, W_enc, b_enc, out_h1, NH, 0, NF, NH, 1);
    linear_k<<<NPTS, NH, NF * 4>>>(qa, NF, W_enc, b_enc, out_h2, NH, 0, NF, NH, 1);

    // 5. encoder_2 -> z = [z1 | z2], decoder -> res
    linear_k<<<NPTS, NH, NH * 4>>>(out_h1, NH, W_enc2, b_enc2, z, NF, 0,  NH, NH, 1);
    linear_k<<<NPTS, NH, NH * 4>>>(out_h2, NH, W_enc2, b_enc2, z, NF, NH, NH, NH, 1);
    linear_k<<<NPTS, NF, NF * 4>>>(z, NF, W_dec, b_dec, res, NF, 0, NF, NF, 0);

    // 6. G = res @ res.T
    gemm_nt_k<<<gNT, 256>>>(res, res, out_G, 1);
}

// round 3
// speedup vs baseline: 2.1577x; 2.1577x over previous
#include <cuda_runtime.h>
#include <cuda_fp16.h>
#include <cstdint>
#include <cstddef>

#define NPTS 10000
#define NF   128
#define NH   64
#define KNN  16
#define ADJ_SCALE     4096.0f
#define INV_ADJ_SCALE (1.0f/4096.0f)

// ---------------- scratch (device globals: allocation-free) ----------------
static __device__ float  g_dist[(size_t)NPTS * NPTS];        // 400 MB
static __device__ __half g_adjh[(size_t)NPTS * NPTS];        // 200 MB
static __device__ __half g_adjl[(size_t)NPTS * NPTS];        // 200 MB
static __device__ __half g_xh[NPTS * NF], g_xl[NPTS * NF];
static __device__ __half g_hh[NPTS * NF], g_hl[NPTS * NF];
static __device__ __half g_rh[NPTS * NF], g_rl[NPTS * NF];
static __device__ float  g_h  [NPTS * NF];
static __device__ float  g_part[4][NPTS * NF];
static __device__ int    g_knn[NPTS * KNN];
static __device__ float  g_sq [NPTS];
static __device__ float  g_qa [NPTS * NF];
static __device__ float  g_qb [NPTS * NF];
static __device__ float  g_z  [NPTS * NF];
static __device__ float  g_res[NPTS * NF];

// ---------------- PTX helpers ----------------
__device__ __forceinline__ void ldsm_x4(uint32_t* r, const __half* p) {
    uint32_t a = (uint32_t)__cvta_generic_to_shared(p);
    asm volatile("ldmatrix.sync.aligned.m8n8.x4.shared.b16 {%0,%1,%2,%3}, [%4];"
                 : "=r"(r[0]), "=r"(r[1]), "=r"(r[2]), "=r"(r[3]) : "r"(a));
}
__device__ __forceinline__ void ldsm_x2(uint32_t* r, const __half* p) {
    uint32_t a = (uint32_t)__cvta_generic_to_shared(p);
    asm volatile("ldmatrix.sync.aligned.m8n8.x2.shared.b16 {%0,%1}, [%2];"
                 : "=r"(r[0]), "=r"(r[1]) : "r"(a));
}
__device__ __forceinline__ void ldsm_x2t(uint32_t* r, const __half* p) {
    uint32_t a = (uint32_t)__cvta_generic_to_shared(p);
    asm volatile("ldmatrix.sync.aligned.m8n8.x2.trans.shared.b16 {%0,%1}, [%2];"
                 : "=r"(r[0]), "=r"(r[1]) : "r"(a));
}
#define MMA16816(d, a, b) \
    asm volatile("mma.sync.aligned.m16n8k16.row.col.f32.f16.f16.f32 " \
                 "{%0,%1,%2,%3},{%4,%5,%6,%7},{%8,%9},{%0,%1,%2,%3};" \
                 : "+f"((d)[0]), "+f"((d)[1]), "+f"((d)[2]), "+f"((d)[3]) \
                 : "r"((a)[0]), "r"((a)[1]), "r"((a)[2]), "r"((a)[3]), \
                   "r"((b)[0]), "r"((b)[1]))
__device__ __forceinline__ void cp16(__half* dst, const void* src, int sz) {
    uint32_t d = (uint32_t)__cvta_generic_to_shared(dst);
    asm volatile("cp.async.ca.shared.global [%0], [%1], 16, %2;"
                 :: "r"(d), "l"(src), "r"(sz));
}

// ---------------- fp32 -> fp16 hi/lo split ----------------
__global__ void split_k(const float* __restrict__ in, __half* __restrict__ hi,
                        __half* __restrict__ lo, size_t n4, float scale) {
    size_t i = (size_t)blockIdx.x * 256 + threadIdx.x;
    if (i >= n4) return;
    float4 v = ((const float4*)in)[i];
    float a = v.x * scale, b = v.y * scale, c = v.z * scale, d = v.w * scale;
    __half ha = __float2half_rn(a), hb = __float2half_rn(b);
    __half hc = __float2half_rn(c), hd = __float2half_rn(d);
    __half la = __float2half_rn(a - __half2float(ha));
    __half lb = __float2half_rn(b - __half2float(hb));
    __half lc = __float2half_rn(c - __half2float(hc));
    __half ld = __float2half_rn(d - __half2float(hd));
    ((__half2*)hi)[2 * i]     = __halves2half2(ha, hb);
    ((__half2*)hi)[2 * i + 1] = __halves2half2(hc, hd);
    ((__half2*)lo)[2 * i]     = __halves2half2(la, lb);
    ((__half2*)lo)[2 * i + 1] = __halves2half2(lc, ld);
}

// ---------------- row squared norms ----------------
__global__ void rownorm_k(const float* __restrict__ x) {
    __shared__ float s[NF];
    const int r = blockIdx.x, t = threadIdx.x;
    float v = x[(size_t)r * NF + t];
    s[t] = v * v;
    __syncthreads();
    for (int o = NF / 2; o > 0; o >>= 1) {
        if (t < o) s[t] += s[t + o];
        __syncthreads();
    }
    if (t == 0) g_sq[r] = s[0];
}

// ---------------- tensor-core C = A @ B^T (K=128), fp16x3 split ----------
// mode 0: dist epilogue; mode 1: plain store
#define LDT 136
__global__ void __launch_bounds__(256) gemm_nt_tc(
    const __half* __restrict__ Ahg, const __half* __restrict__ Alg,
    const __half* __restrict__ Bhg, const __half* __restrict__ Blg,
    float* __restrict__ C, int mode)
{
    extern __shared__ __half sm[];
    __half* sAh = sm;
    __half* sAl = sm + 128 * LDT;
    __half* sBh = sm + 2 * 128 * LDT;
    __half* sBl = sm + 3 * 128 * LDT;
    const int bm = blockIdx.y * 128, bn = blockIdx.x * 128;
    const int tid = threadIdx.x;

    {   // load all four 128x128 tiles
        const int r = tid >> 1;
        const int segbase = (tid & 1) * 64;
        const bool aok = (bm + r) < NPTS;
        const bool bok = (bn + r) < NPTS;
        const uint4 zz = make_uint4(0, 0, 0, 0);
#pragma unroll
        for (int i = 0; i < 8; i++) {
            const int col = segbase + i * 8;
            uint4 vah = aok ? *(const uint4*)(Ahg + (size_t)(bm + r) * NF + col) : zz;
            uint4 val = aok ? *(const uint4*)(Alg + (size_t)(bm + r) * NF + col) : zz;
            uint4 vbh = bok ? *(const uint4*)(Bhg + (size_t)(bn + r) * NF + col) : zz;
            uint4 vbl = bok ? *(const uint4*)(Blg + (size_t)(bn + r) * NF + col) : zz;
            *(uint4*)(sAh + r * LDT + col) = vah;
            *(uint4*)(sAl + r * LDT + col) = val;
            *(uint4*)(sBh + r * LDT + col) = vbh;
            *(uint4*)(sBl + r * LDT + col) = vbl;
        }
    }
    __syncthreads();

    const int warp = tid >> 5, lane = tid & 31;
    const int wm = warp >> 2, wn = warp & 3;        // 2 x 4 warps
    const int m0 = wm * 64, n0 = wn * 32;
    const int arow = (lane & 7) + ((lane >> 3) & 1) * 8;
    const int acol = (lane >> 4) * 8;
    const int brow = (lane & 7);
    const int bcol = ((lane >> 3) & 1) * 8;

    float acc[4][4][4];
#pragma unroll
    for (int a = 0; a < 4; a++)
#pragma unroll
        for (int b = 0; b < 4; b++)
#pragma unroll
            for (int c = 0; c < 4; c++) acc[a][b][c] = 0.f;

#pragma unroll
    for (int ks = 0; ks < 8; ks++) {
        const int k0 = ks * 16;
        uint32_t ah[4][4], al[4][4], bh[4][2], bl[4][2];
#pragma unroll
        for (int mf = 0; mf < 4; mf++) {
            const int row = m0 + mf * 16 + arow;
            ldsm_x4(ah[mf], sAh + row * LDT + k0 + acol);
            ldsm_x4(al[mf], sAl + row * LDT + k0 + acol);
        }
#pragma unroll
        for (int nf = 0; nf < 4; nf++) {
            const int row = n0 + nf * 8 + brow;
            ldsm_x2(bh[nf], sBh + row * LDT + k0 + bcol);
            ldsm_x2(bl[nf], sBl + row * LDT + k0 + bcol);
        }
#pragma unroll
        for (int mf = 0; mf < 4; mf++)
#pragma unroll
            for (int nf = 0; nf < 4; nf++) {
                MMA16816(acc[mf][nf], ah[mf], bh[nf]);
                MMA16816(acc[mf][nf], ah[mf], bl[nf]);
                MMA16816(acc[mf][nf], al[mf], bh[nf]);
            }
    }

    // epilogue
    const int lr = lane >> 2, lc2 = (lane & 3) * 2;
#pragma unroll
    for (int mf = 0; mf < 4; mf++) {
#pragma unroll
        for (int nf = 0; nf < 4; nf++) {
            const int m = bm + m0 + mf * 16 + lr;
            const int n = bn + n0 + nf * 8 + lc2;
            if (n >= NPTS) continue;
            float c0 = acc[mf][nf][0], c1 = acc[mf][nf][1];
            float c2 = acc[mf][nf][2], c3 = acc[mf][nf][3];
            if (mode == 0) {
                const float sn0 = g_sq[n], sn1 = g_sq[n + 1];
                if (m < NPTS) {
                    const float smv = g_sq[m];
                    c0 = smv + sn0 - 2.f * c0;
                    c1 = smv + sn1 - 2.f * c1;
                    if (m == n)     c0 += 1e30f;
                    if (m == n + 1) c1 += 1e30f;
                }
                if (m + 8 < NPTS) {
                    const float smv = g_sq[m + 8];
                    c2 = smv + sn0 - 2.f * c2;
                    c3 = smv + sn1 - 2.f * c3;
                    if (m + 8 == n)     c2 += 1e30f;
                    if (m + 8 == n + 1) c3 += 1e30f;
                }
            }
            if (m < NPTS) {
                float2 v; v.x = c0; v.y = c1;
                *(float2*)(C + (size_t)m * NPTS + n) = v;
            }
            if (m + 8 < NPTS) {
                float2 v; v.x = c2; v.y = c3;
                *(float2*)(C + (size_t)(m + 8) * NPTS + n) = v;
            }
        }
    }
}

// ---------------- tensor-core hop: part[by] = adjs[:, krange] @ H --------
// A fp16-split (pre-scaled), H fp16-split [K][128]. 3-stage cp.async.
#define HLDA 24
#define HLDB 136
#define HSTAGE 10496   // halves per stage: 2*128*24 + 2*16*136
__global__ void __launch_bounds__(256) hop_tc(
    const __half* __restrict__ Ahg, const __half* __restrict__ Alg,
    const __half* __restrict__ Bhg, const __half* __restrict__ Blg)
{
    extern __shared__ __half sm[];
    const int bm = blockIdx.x * 128;
    const int by = blockIdx.y;
    const int kbase = (by == 0) ? 0 : 2512 + (by - 1) * 2496;
    const int ksize = (by == 0) ? 2512 : 2496;
    const int nk = ksize / 16;
    float* __restrict__ Cp = g_part[by];
    const int tid = threadIdx.x;

    const int ar = tid >> 1, aseg = (tid & 1) * 8;     // A: 2 thr/row
    const int bkr = tid >> 4, bseg = (tid & 15) * 8;   // B: 16 thr/row
    const bool aok = (bm + ar) < NPTS;
    const int asz = aok ? 16 : 0;
    const __half* gAh = Ahg + (size_t)(aok ? (bm + ar) : 0) * NPTS;
    const __half* gAl = Alg + (size_t)(aok ? (bm + ar) : 0) * NPTS;

    auto issue = [&](int kc) {
        __half* st = sm + (kc % 3) * HSTAGE;
        const int kpos = kbase + kc * 16;
        cp16(st + ar * HLDA + aseg,                 gAh + kpos + aseg, asz);
        cp16(st + 3072 + ar * HLDA + aseg,          gAl + kpos + aseg, asz);
        cp16(st + 6144 + bkr * HLDB + bseg,         Bhg + (size_t)(kpos + bkr) * NF + bseg, 16);
        cp16(st + 6144 + 2176 + bkr * HLDB + bseg,  Blg + (size_t)(kpos + bkr) * NF + bseg, 16);
        asm volatile("cp.async.commit_group;");
    };
    issue(0);
    issue(1);

    const int warp = tid >> 5, lane = tid & 31;
    const int wm = warp >> 2, wn = warp & 3;
    const int m0 = wm * 64, n0 = wn * 32;
    const int arow = (lane & 7) + ((lane >> 3) & 1) * 8;
    const int acol = (lane >> 4) * 8;
    const int bk   = (lane & 7) + ((lane >> 3) & 1) * 8;   // trans: k-row in stage

    float acc[4][4][4];
#pragma unroll
    for (int a = 0; a < 4; a++)
#pragma unroll
        for (int b = 0; b < 4; b++)
#pragma unroll
            for (int c = 0; c < 4; c++) acc[a][b][c] = 0.f;

    for (int kc = 0; kc < nk; kc++) {
        asm volatile("cp.async.wait_group 1;");
        __syncthreads();
        if (kc + 2 < nk) issue(kc + 2);
        __half* st  = sm + (kc % 3) * HSTAGE;
        __half* sAh = st;
        __half* sAl = st + 3072;
        __half* sBh = st + 6144;
        __half* sBl = st + 8320;

        uint32_t ah[4][4], al[4][4], bh[4][2], bl[4][2];
#pragma unroll
        for (int mf = 0; mf < 4; mf++)
            ldsm_x4(ah[mf], sAh + (m0 + mf * 16 + arow) * HLDA + acol);
#pragma unroll
        for (int nf = 0; nf < 4; nf++) {
            ldsm_x2t(bh[nf], sBh + bk * HLDB + n0 + nf * 8);
            ldsm_x2t(bl[nf], sBl + bk * HLDB + n0 + nf * 8);
        }
#pragma unroll
        for (int mf = 0; mf < 4; mf++)
#pragma unroll
            for (int nf = 0; nf < 4; nf++) {
                MMA16816(acc[mf][nf], ah[mf], bh[nf]);
                MMA16816(acc[mf][nf], ah[mf], bl[nf]);
            }
#pragma unroll
        for (int mf = 0; mf < 4; mf++)
            ldsm_x4(al[mf], sAl + (m0 + mf * 16 + arow) * HLDA + acol);
#pragma unroll
        for (int mf = 0; mf < 4; mf++)
#pragma unroll
            for (int nf = 0; nf < 4; nf++)
                MMA16816(acc[mf][nf], al[mf], bh[nf]);
    }

    const int lr = lane >> 2, lc2 = (lane & 3) * 2;
#pragma unroll
    for (int mf = 0; mf < 4; mf++)
#pragma unroll
        for (int nf = 0; nf < 4; nf++) {
            const int m = bm + m0 + mf * 16 + lr;
            const int n = n0 + nf * 8 + lc2;
            if (m < NPTS) {
                float2 v; v.x = acc[mf][nf][0]; v.y = acc[mf][nf][1];
                *(float2*)(Cp + (size_t)m * NF + n) = v;
            }
            if (m + 8 < NPTS) {
                float2 v; v.x = acc[mf][nf][2]; v.y = acc[mf][nf][3];
                *(float2*)(Cp + (size_t)(m + 8) * NF + n) = v;
            }
        }
}

// out = 0.5/ADJ_SCALE * (p0+p1+p2+p3) + 0.5*x ; also emits fp16 split
__global__ void combine_tc_k(const float* __restrict__ x) {
    const int i = blockIdx.x * 256 + threadIdx.x;
    float s = g_part[0][i] + g_part[1][i] + g_part[2][i] + g_part[3][i];
    float o = 0.5f * INV_ADJ_SCALE * s + 0.5f * x[i];
    g_h[i] = o;
    __half h = __float2half_rn(o);
    g_hh[i] = h;
    g_hl[i] = __float2half_rn(o - __half2float(h));
}

// ---------------- top-16 per row (lexicographic: (dist, idx) min) ---------
__global__ void __launch_bounds__(256) topk_k() {
    __shared__ float sv[4096];
    __shared__ int   si[4096];
    __shared__ float rv[256];
    __shared__ int   ri[256];
    __shared__ int   rp[256];
    const int r = blockIdx.x, t = threadIdx.x;
    const float* drow = g_dist + (size_t)r * NPTS;

    float lv[KNN]; int li[KNN];
#pragma unroll
    for (int i = 0; i < KNN; i++) { lv[i] = 3.4e38f; li[i] = 0x7fffffff; }
    float wv = 3.4e38f; int wi = 0x7fffffff, wp = 0;

    for (int j = t; j < NPTS; j += 256) {
        const float v = drow[j];
        if (v < wv || (v == wv && j < wi)) {
            lv[wp] = v; li[wp] = j;
            wv = -3.4e38f; wi = -1;
#pragma unroll
            for (int i = 0; i < KNN; i++) {
                if (lv[i] > wv || (lv[i] == wv && li[i] > wi)) {
                    wv = lv[i]; wi = li[i]; wp = i;
                }
            }
        }
    }
#pragma unroll
    for (int i = 0; i < KNN; i++) { sv[t * KNN + i] = lv[i]; si[t * KNN + i] = li[i]; }
    __syncthreads();

    for (int sel = 0; sel < KNN; sel++) {
        float bv = 3.5e38f; int bi = 0x7fffffff, bp = -1;
        for (int q = t; q < 4096; q += 256) {
            const float v = sv[q]; const int ii = si[q];
            if (v < bv || (v == bv && ii < bi)) { bv = v; bi = ii; bp = q; }
        }
        rv[t] = bv; ri[t] = bi; rp[t] = bp;
        __syncthreads();
        for (int o = 128; o > 0; o >>= 1) {
            if (t < o) {
                if (rv[t + o] < rv[t] || (rv[t + o] == rv[t] && ri[t + o] < ri[t])) {
                    rv[t] = rv[t + o]; ri[t] = ri[t + o]; rp[t] = rp[t + o];
                }
            }
            __syncthreads();
        }
        if (t == 0) {
            g_knn[r * KNN + sel] = ri[0];
            sv[rp[0]] = 3.5e38f; si[rp[0]] = 0x7fffffff;
        }
        __syncthreads();
    }
}

// ---------------- sparse knn hop ----------------
__global__ void sparse_hop_k(const float* __restrict__ Hin,
                             const float* __restrict__ x,
                             float* __restrict__ Hout) {
    __shared__ int nb[KNN];
    const int r = blockIdx.x, t = threadIdx.x;
    if (t < KNN) nb[t] = g_knn[r * KNN + t];
    __syncthreads();
    float s = 0.f;
#pragma unroll
    for (int i = 0; i < KNN; i++) s += Hin[(size_t)nb[i] * NF + t];
    Hout[(size_t)r * NF + t] = 0.03125f * s + 0.5f * x[(size_t)r * NF + t];
}

// ---------------- small dense layers ----------------
__global__ void linear_k(const float* __restrict__ In, int ldin,
                         const float* __restrict__ W, const float* __restrict__ b,
                         float* __restrict__ Out, int ldout, int coff,
                         int Kdim, int Ndim, int dorelu) {
    extern __shared__ float rs[];
    const int r = blockIdx.x, t = threadIdx.x;
    for (int k = t; k < Kdim; k += blockDim.x) rs[k] = In[(size_t)r * ldin + k];
    __syncthreads();
    float acc = b[t];
    for (int k = 0; k < Kdim; k++) acc = fmaf(rs[k], W[k * Ndim + t], acc);
    if (dorelu) acc = fmaxf(acc, 0.f);
    Out[(size_t)r * ldout + coff + t] = acc;
}

// ---------------- launch ---------------------------------------------------
extern "C" void kernel_launch(void* const* d_in, const int* in_sizes, int n_in,
                              void* d_out, int out_size) {
    (void)in_sizes; (void)n_in; (void)out_size;
    const float* x      = (const float*)d_in[0];
    const float* adj    = (const float*)d_in[1];
    const float* W_enc  = (const float*)d_in[2];
    const float* b_enc  = (const float*)d_in[3];
    const float* W_enc2 = (const float*)d_in[4];
    const float* b_enc2 = (const float*)d_in[5];
    const float* W_dec  = (const float*)d_in[6];
    const float* b_dec  = (const float*)d_in[7];

    float* out    = (float*)d_out;
    float* out_h1 = out;
    float* out_h2 = out + (size_t)NPTS * NH;
    float* out_G  = out + (size_t)2 * NPTS * NH;

    __half *adjh, *adjl, *xh, *xl, *hh, *hl, *rh, *rl;
    float *h, *qa, *qb, *z, *res, *dist;
    cudaGetSymbolAddress((void**)&adjh, g_adjh);
    cudaGetSymbolAddress((void**)&adjl, g_adjl);
    cudaGetSymbolAddress((void**)&xh,   g_xh);
    cudaGetSymbolAddress((void**)&xl,   g_xl);
    cudaGetSymbolAddress((void**)&hh,   g_hh);
    cudaGetSymbolAddress((void**)&hl,   g_hl);
    cudaGetSymbolAddress((void**)&rh,   g_rh);
    cudaGetSymbolAddress((void**)&rl,   g_rl);
    cudaGetSymbolAddress((void**)&h,    g_h);
    cudaGetSymbolAddress((void**)&qa,   g_qa);
    cudaGetSymbolAddress((void**)&qb,   g_qb);
    cudaGetSymbolAddress((void**)&z,    g_z);
    cudaGetSymbolAddress((void**)&res,  g_res);
    cudaGetSymbolAddress((void**)&dist, g_dist);

    const int GEMM_SMEM = 4 * 128 * LDT * 2;   // 139264 B
    const int HOP_SMEM  = 3 * HSTAGE * 2;      // 62976 B
    cudaFuncSetAttribute(gemm_nt_tc, cudaFuncAttributeMaxDynamicSharedMemorySize, GEMM_SMEM);
    cudaFuncSetAttribute(hop_tc,     cudaFuncAttributeMaxDynamicSharedMemorySize, HOP_SMEM);

    const dim3 gNT(79, 79);
    const dim3 gHop(79, 4);

    // 1-2: fp16 splits of adj (scaled) and x
    split_k<<<97657, 256>>>(adj, adjh, adjl, (size_t)NPTS * NPTS / 4, ADJ_SCALE);
    split_k<<<1250, 256>>>(x, xh, xl, (size_t)NPTS * NF / 4, 1.0f);
    // 3: row norms; 4: distances; 5: knn
    rownorm_k<<<NPTS, NF>>>(x);
    gemm_nt_tc<<<gNT, 256, GEMM_SMEM>>>(xh, xl, xh, xl, dist, 0);
    topk_k<<<NPTS, 256>>>();

    // 6+: dense (adj) propagation, 5 hops (hop1 is launch #6 for ncu)
    hop_tc<<<gHop, 256, HOP_SMEM>>>(adjh, adjl, xh, xl);
    combine_tc_k<<<5000, 256>>>(x);
    for (int i = 1; i < 5; i++) {
        hop_tc<<<gHop, 256, HOP_SMEM>>>(adjh, adjl, hh, hl);
        combine_tc_k<<<5000, 256>>>(x);
    }

    // sparse (knn) propagation, 5 hops: x->qa->qb->qa->qb->qa
    sparse_hop_k<<<NPTS, NF>>>(x,  x, qa);
    sparse_hop_k<<<NPTS, NF>>>(qa, x, qb);
    sparse_hop_k<<<NPTS, NF>>>(qb, x, qa);
    sparse_hop_k<<<NPTS, NF>>>(qa, x, qb);
    sparse_hop_k<<<NPTS, NF>>>(qb, x, qa);

    // encoders -> h1, h2
    linear_k<<<NPTS, NH, NF * 4>>>(h,  NF, W_enc, b_enc, out_h1, NH, 0, NF, NH, 1);
    linear_k<<<NPTS, NH, NF * 4>>>(qa, NF, W_enc, b_enc, out_h2, NH, 0, NF, NH, 1);

    // encoder_2 -> z = [z1 | z2], decoder -> res
    linear_k<<<NPTS, NH, NH * 4>>>(out_h1, NH, W_enc2, b_enc2, z, NF, 0,  NH, NH, 1);
    linear_k<<<NPTS, NH, NH * 4>>>(out_h2, NH, W_enc2, b_enc2, z, NF, NH, NH, NH, 1);
    linear_k<<<NPTS, NF, NF * 4>>>(z, NF, W_dec, b_dec, res, NF, 0, NF, NF, 0);

    // res split + G = res @ res.T
    split_k<<<1250, 256>>>(res, rh, rl, (size_t)NPTS * NF / 4, 1.0f);
    gemm_nt_tc<<<gNT, 256, GEMM_SMEM>>>(rh, rl, rh, rl, out_G, 1);
}

// round 5
// speedup vs baseline: 2.1747x; 1.0079x over previous
#include <cuda_runtime.h>
#include <cuda_fp16.h>
#include <cstdint>
#include <cstddef>

#define NPTS 10000
#define NF   128
#define NH   64
#define KNN  16
#define ADJ_SCALE     4096.0f
#define INV_ADJ_SCALE (1.0f/4096.0f)
#define LDS  72     // hop smem stride (halves) for 64-col K tiles
#define LDB2 136    // hop B smem stride (halves)
#define LDT  136    // gemm3 smem stride (halves), K=128 + 8 pad

// ---------------- scratch (device globals: allocation-free) ----------------
static __device__ float  g_dist[(size_t)NPTS * NPTS];        // 400 MB
static __device__ __half g_adjh[(size_t)NPTS * NPTS];        // 200 MB, scaled x4096
static __device__ __half g_xh[NPTS * NF], g_xl[NPTS * NF];
static __device__ __half g_rh[NPTS * NF], g_rl[NPTS * NF];
static __device__ __half g_hh [NPTS * NF];                   // h fp16 (hop feedback)
static __device__ float  g_h  [NPTS * NF];
static __device__ float  g_part[4][NPTS * NF];
static __device__ int    g_knn[NPTS * KNN];
static __device__ float  g_sq [NPTS];
static __device__ float  g_qa [NPTS * NF];
static __device__ float  g_qb [NPTS * NF];
static __device__ float  g_z  [NPTS * NF];
static __device__ float  g_res[NPTS * NF];

// ---------------- PTX helpers ----------------
__device__ __forceinline__ void ldsm_x4(uint32_t* r, const __half* p) {
    uint32_t a = (uint32_t)__cvta_generic_to_shared(p);
    asm volatile("ldmatrix.sync.aligned.m8n8.x4.shared.b16 {%0,%1,%2,%3}, [%4];"
                 : "=r"(r[0]), "=r"(r[1]), "=r"(r[2]), "=r"(r[3]) : "r"(a));
}
__device__ __forceinline__ void ldsm_x2(uint32_t* r, const __half* p) {
    uint32_t a = (uint32_t)__cvta_generic_to_shared(p);
    asm volatile("ldmatrix.sync.aligned.m8n8.x2.shared.b16 {%0,%1}, [%2];"
                 : "=r"(r[0]), "=r"(r[1]) : "r"(a));
}
__device__ __forceinline__ void ldsm_x2t(uint32_t* r, const __half* p) {
    uint32_t a = (uint32_t)__cvta_generic_to_shared(p);
    asm volatile("ldmatrix.sync.aligned.m8n8.x2.trans.shared.b16 {%0,%1}, [%2];"
                 : "=r"(r[0]), "=r"(r[1]) : "r"(a));
}
#define MMA16816(d, a, b) \
    asm volatile("mma.sync.aligned.m16n8k16.row.col.f32.f16.f16.f32 " \
                 "{%0,%1,%2,%3},{%4,%5,%6,%7},{%8,%9},{%0,%1,%2,%3};" \
                 : "+f"((d)[0]), "+f"((d)[1]), "+f"((d)[2]), "+f"((d)[3]) \
                 : "r"((a)[0]), "r"((a)[1]), "r"((a)[2]), "r"((a)[3]), \
                   "r"((b)[0]), "r"((b)[1]))
__device__ __forceinline__ void cp16z(__half* dst, const void* src, int srcbytes) {
    uint32_t d = (uint32_t)__cvta_generic_to_shared(dst);
    asm volatile("cp.async.ca.shared.global [%0], [%1], 16, %2;"
                 :: "r"(d), "l"(src), "r"(srcbytes));
}
#define CP_COMMIT() asm volatile("cp.async.commit_group;")
#define CP_WAIT1()  asm volatile("cp.async.wait_group 1;")
#define CP_WAIT0()  asm volatile("cp.async.wait_group 0;")

// ---------------- adj -> fp16 hi only (scaled) ----------------
__global__ void split_adj_k(const float* __restrict__ in, __half* __restrict__ hi,
                            size_t n4) {
    size_t i = (size_t)blockIdx.x * 256 + threadIdx.x;
    if (i >= n4) return;
    float4 v = ((const float4*)in)[i];
    ((__half2*)hi)[2 * i]     = __halves2half2(__float2half_rn(v.x * ADJ_SCALE),
                                               __float2half_rn(v.y * ADJ_SCALE));
    ((__half2*)hi)[2 * i + 1] = __halves2half2(__float2half_rn(v.z * ADJ_SCALE),
                                               __float2half_rn(v.w * ADJ_SCALE));
}

// ---------------- fp32 -> fp16 hi/lo split (separate arrays) --------------
__global__ void split_k(const float* __restrict__ in, __half* __restrict__ hi,
                        __half* __restrict__ lo, size_t n4) {
    size_t i = (size_t)blockIdx.x * 256 + threadIdx.x;
    if (i >= n4) return;
    float4 v = ((const float4*)in)[i];
    __half ha = __float2half_rn(v.x), hb = __float2half_rn(v.y);
    __half hc = __float2half_rn(v.z), hd = __float2half_rn(v.w);
    ((__half2*)hi)[2 * i]     = __halves2half2(ha, hb);
    ((__half2*)hi)[2 * i + 1] = __halves2half2(hc, hd);
    ((__half2*)lo)[2 * i]     = __halves2half2(__float2half_rn(v.x - __half2float(ha)),
                                               __float2half_rn(v.y - __half2float(hb)));
    ((__half2*)lo)[2 * i + 1] = __halves2half2(__float2half_rn(v.z - __half2float(hc)),
                                               __float2half_rn(v.w - __half2float(hd)));
}

// ---------------- row squared norms ----------------
__global__ void rownorm_k(const float* __restrict__ x) {
    __shared__ float s[NF];
    const int r = blockIdx.x, t = threadIdx.x;
    float v = x[(size_t)r * NF + t];
    s[t] = v * v;
    __syncthreads();
    for (int o = NF / 2; o > 0; o >>= 1) {
        if (t < o) s[t] += s[t + o];
        __syncthreads();
    }
    if (t == 0) g_sq[r] = s[0];
}

// ---- C = A @ B^T, 3-term fp16 split, 64x128 tile, K=128, occ 2 -----------
// mode 0: dist epilogue; mode 1: plain store
#define G3_SMEM (384 * LDT * 2)    // 104448 B
__global__ void __launch_bounds__(256, 2) gemm3_tc(
    const __half* __restrict__ Ahg, const __half* __restrict__ Alg,
    const __half* __restrict__ Bhg, const __half* __restrict__ Blg,
    float* __restrict__ C, int mode)
{
    extern __shared__ __half sm[];
    __half* sAh = sm;
    __half* sAl = sm + 64 * LDT;
    __half* sBh = sm + 128 * LDT;
    __half* sBl = sm + 256 * LDT;
    const int bm = blockIdx.y * 64, bn = blockIdx.x * 128;
    const int tid = threadIdx.x;

    {   // cp.async load: A tiles 64x128, B tiles 128x128
        const int ra = tid >> 2, ca = (tid & 3) * 32;
        const int rb = tid >> 1, cb = (tid & 1) * 64;
        const bool aok = (bm + ra) < NPTS;
        const bool bok = (bn + rb) < NPTS;
        const __half* gah = Ahg + (size_t)(aok ? bm + ra : 0) * NF + ca;
        const __half* gal = Alg + (size_t)(aok ? bm + ra : 0) * NF + ca;
        const __half* gbh = Bhg + (size_t)(bok ? bn + rb : 0) * NF + cb;
        const __half* gbl = Blg + (size_t)(bok ? bn + rb : 0) * NF + cb;
        const int asz = aok ? 16 : 0, bsz = bok ? 16 : 0;
#pragma unroll
        for (int i = 0; i < 4; i++) {
            cp16z(sAh + ra * LDT + ca + i * 8, gah + i * 8, asz);
            cp16z(sAl + ra * LDT + ca + i * 8, gal + i * 8, asz);
        }
#pragma unroll
        for (int i = 0; i < 8; i++) {
            cp16z(sBh + rb * LDT + cb + i * 8, gbh + i * 8, bsz);
            cp16z(sBl + rb * LDT + cb + i * 8, gbl + i * 8, bsz);
        }
        CP_COMMIT();
        CP_WAIT0();
    }
    __syncthreads();

    const int warp = tid >> 5, lane = tid & 31;
    const int wm = warp >> 2, wn = warp & 3;       // 2 x 4 warps, warp tile 32x32
    const int m0 = wm * 32, n0 = wn * 32;
    const int arow = (lane & 7) + ((lane >> 3) & 1) * 8;
    const int acol = (lane >> 4) * 8;
    const int brow = (lane & 7);
    const int bcol = ((lane >> 3) & 1) * 8;

    float acc[2][4][4];
#pragma unroll
    for (int a = 0; a < 2; a++)
#pragma unroll
        for (int b = 0; b < 4; b++)
#pragma unroll
            for (int c = 0; c < 4; c++) acc[a][b][c] = 0.f;

#pragma unroll
    for (int ks = 0; ks < 8; ks++) {
        const int k0 = ks * 16;
        uint32_t ah[2][4], al[2][4], bh[4][2], bl[4][2];
#pragma unroll
        for (int mf = 0; mf < 2; mf++) {
            const int row = m0 + mf * 16 + arow;
            ldsm_x4(ah[mf], sAh + row * LDT + k0 + acol);
            ldsm_x4(al[mf], sAl + row * LDT + k0 + acol);
        }
#pragma unroll
        for (int nf = 0; nf < 4; nf++) {
            const int row = n0 + nf * 8 + brow;
            ldsm_x2(bh[nf], sBh + row * LDT + k0 + bcol);
            ldsm_x2(bl[nf], sBl + row * LDT + k0 + bcol);
        }
#pragma unroll
        for (int mf = 0; mf < 2; mf++)
#pragma unroll
            for (int nf = 0; nf < 4; nf++) {
                MMA16816(acc[mf][nf], ah[mf], bh[nf]);
                MMA16816(acc[mf][nf], ah[mf], bl[nf]);
                MMA16816(acc[mf][nf], al[mf], bh[nf]);
            }
    }

    const int lr = lane >> 2, lc2 = (lane & 3) * 2;
#pragma unroll
    for (int mf = 0; mf < 2; mf++) {
#pragma unroll
        for (int nf = 0; nf < 4; nf++) {
            const int m = bm + m0 + mf * 16 + lr;
            const int n = bn + n0 + nf * 8 + lc2;
            if (n >= NPTS) continue;
            float c0 = acc[mf][nf][0], c1 = acc[mf][nf][1];
            float c2 = acc[mf][nf][2], c3 = acc[mf][nf][3];
            if (mode == 0) {
                const float sn0 = g_sq[n], sn1 = g_sq[n + 1];
                if (m < NPTS) {
                    const float smv = g_sq[m];
                    c0 = smv + sn0 - 2.f * c0;
                    c1 = smv + sn1 - 2.f * c1;
                    if (m == n)     c0 += 1e30f;
                    if (m == n + 1) c1 += 1e30f;
                }
                if (m + 8 < NPTS) {
                    const float smv = g_sq[m + 8];
                    c2 = smv + sn0 - 2.f * c2;
                    c3 = smv + sn1 - 2.f * c3;
                    if (m + 8 == n)     c2 += 1e30f;
                    if (m + 8 == n + 1) c3 += 1e30f;
                }
            }
            if (m < NPTS) {
                float2 v; v.x = c0; v.y = c1;
                *(float2*)(C + (size_t)m * NPTS + n) = v;
            }
            if (m + 8 < NPTS) {
                float2 v; v.x = c2; v.y = c3;
                *(float2*)(C + (size_t)(m + 8) * NPTS + n) = v;
            }
        }
    }
}

// ---- hop: part[by] = adjh[:, kchunk] @ H, single-term fp16, 3-stage ------
#define HBUFA (128 * LDS)          // 9216 halves
#define HBUFB (64 * LDB2)          // 8704 halves
#define HBUF  (HBUFA + HBUFB)      // 17920 halves per stage
__global__ void __launch_bounds__(256, 2) hop_tc2(
    const __half* __restrict__ Ag, const __half* __restrict__ Bg, int ldb)
{
    extern __shared__ __half sm[];
    const int bm = blockIdx.x * 128;
    const int by = blockIdx.y;
    const int kbase = by * 2560;
    const int kend = (kbase + 2560 < NPTS) ? kbase + 2560 : NPTS;
    const int nst = (kend - kbase + 63) / 64;
    float* __restrict__ Cp = g_part[by];
    const int tid = threadIdx.x;

    const int ar = tid >> 1, acb = (tid & 1) * 32;     // A: 2 thr/row, 4 cp16
    const int br = tid >> 2, bcb = (tid & 3) * 32;     // B: 4 thr/row, 4 cp16
    const bool aok = (bm + ar) < NPTS;
    const __half* gA = Ag + (size_t)(aok ? bm + ar : 0) * NPTS;

    auto issue = [&](int s) {
        __half* st = sm + (s % 3) * HBUF;
        __half* sA = st;
        __half* sB = st + HBUFA;
        const int kpos = kbase + s * 64;
        const int vk = kend - kpos < 64 ? kend - kpos : 64;   // valid K cols
#pragma unroll
        for (int i = 0; i < 4; i++) {
            const int c = acb + i * 8;
            int vb = (vk - c) * 2;
            vb = vb < 0 ? 0 : (vb > 16 ? 16 : vb);
            cp16z(sA + ar * LDS + c, gA + kpos + c, aok ? vb : 0);
        }
        const int brow_ok = (br < vk) ? 1 : 0;
        const __half* gB = Bg + (size_t)(brow_ok ? kpos + br : 0) * ldb;
#pragma unroll
        for (int i = 0; i < 4; i++)
            cp16z(sB + br * LDB2 + bcb + i * 8, gB + bcb + i * 8, brow_ok ? 16 : 0);
        CP_COMMIT();
    };
    issue(0);
    issue(1);

    const int warp = tid >> 5, lane = tid & 31;
    const int wm = warp >> 2, wn = warp & 3;
    const int m0 = wm * 64, n0 = wn * 32;
    const int arow = (lane & 7) + ((lane >> 3) & 1) * 8;
    const int acol = (lane >> 4) * 8;
    const int bk = lane & 15;

    float acc[4][4][4];
#pragma unroll
    for (int a = 0; a < 4; a++)
#pragma unroll
        for (int b = 0; b < 4; b++)
#pragma unroll
            for (int c = 0; c < 4; c++) acc[a][b][c] = 0.f;

    for (int s = 0; s < nst; s++) {
        CP_WAIT1();
        __syncthreads();
        if (s + 2 < nst) issue(s + 2);
        __half* st = sm + (s % 3) * HBUF;
        __half* sA = st;
        __half* sB = st + HBUFA;
#pragma unroll
        for (int kk = 0; kk < 4; kk++) {
            const int k0 = kk * 16;
            uint32_t af[4][4], bf[4][2];
#pragma unroll
            for (int mf = 0; mf < 4; mf++)
                ldsm_x4(af[mf], sA + (m0 + mf * 16 + arow) * LDS + k0 + acol);
#pragma unroll
            for (int nf = 0; nf < 4; nf++)
                ldsm_x2t(bf[nf], sB + (k0 + bk) * LDB2 + n0 + nf * 8);
#pragma unroll
            for (int mf = 0; mf < 4; mf++)
#pragma unroll
                for (int nf = 0; nf < 4; nf++)
                    MMA16816(acc[mf][nf], af[mf], bf[nf]);
        }
    }

    const int lr = lane >> 2, lc2 = (lane & 3) * 2;
#pragma unroll
    for (int mf = 0; mf < 4; mf++)
#pragma unroll
        for (int nf = 0; nf < 4; nf++) {
            const int m = bm + m0 + mf * 16 + lr;
            const int n = n0 + nf * 8 + lc2;
            if (m < NPTS) {
                float2 v; v.x = acc[mf][nf][0]; v.y = acc[mf][nf][1];
                *(float2*)(Cp + (size_t)m * NF + n) = v;
            }
            if (m + 8 < NPTS) {
                float2 v; v.x = acc[mf][nf][2]; v.y = acc[mf][nf][3];
                *(float2*)(Cp + (size_t)(m + 8) * NF + n) = v;
            }
        }
}

// h = 0.5/ADJ_SCALE * (p0+p1+p2+p3) + 0.5*x ; also emits fp16 hi
__global__ void combine_tc_k(const float* __restrict__ x) {
    const int i = blockIdx.x * 256 + threadIdx.x;
    float s = g_part[0][i] + g_part[1][i] + g_part[2][i] + g_part[3][i];
    float o = 0.5f * INV_ADJ_SCALE * s + 0.5f * x[i];
    g_h[i] = o;
    g_hh[i] = __float2half_rn(o);
}

// ---------------- top-16 per row (lexicographic: (dist, idx) min) ---------
__global__ void __launch_bounds__(256) topk_k() {
    __shared__ float sv[4096];
    __shared__ int   si[4096];
    __shared__ float rv[256];
    __shared__ int   ri[256];
    __shared__ int   rp[256];
    const int r = blockIdx.x, t = threadIdx.x;
    const float* drow = g_dist + (size_t)r * NPTS;

    float lv[KNN]; int li[KNN];
#pragma unroll
    for (int i = 0; i < KNN; i++) { lv[i] = 3.4e38f; li[i] = 0x7fffffff; }
    float wv = 3.4e38f; int wi = 0x7fffffff, wp = 0;

    for (int j = t; j < NPTS; j += 256) {
        const float v = drow[j];
        if (v < wv || (v == wv && j < wi)) {
            lv[wp] = v; li[wp] = j;
            wv = -3.4e38f; wi = -1;
#pragma unroll
            for (int i = 0; i < KNN; i++) {
                if (lv[i] > wv || (lv[i] == wv && li[i] > wi)) {
                    wv = lv[i]; wi = li[i]; wp = i;
                }
            }
        }
    }
#pragma unroll
    for (int i = 0; i < KNN; i++) { sv[t * KNN + i] = lv[i]; si[t * KNN + i] = li[i]; }
    __syncthreads();

    for (int sel = 0; sel < KNN; sel++) {
        float bv = 3.5e38f; int bi = 0x7fffffff, bp = -1;
        for (int q = t; q < 4096; q += 256) {
            const float v = sv[q]; const int ii = si[q];
            if (v < bv || (v == bv && ii < bi)) { bv = v; bi = ii; bp = q; }
        }
        rv[t] = bv; ri[t] = bi; rp[t] = bp;
        __syncthreads();
        for (int o = 128; o > 0; o >>= 1) {
            if (t < o) {
                if (rv[t + o] < rv[t] || (rv[t + o] == rv[t] && ri[t + o] < ri[t])) {
                    rv[t] = rv[t + o]; ri[t] = ri[t + o]; rp[t] = rp[t + o];
                }
            }
            __syncthreads();
        }
        if (t == 0) {
            g_knn[r * KNN + sel] = ri[0];
            sv[rp[0]] = 3.5e38f; si[rp[0]] = 0x7fffffff;
        }
        __syncthreads();
    }
}

// ---------------- sparse knn hop ----------------
__global__ void sparse_hop_k(const float* __restrict__ Hin,
                             const float* __restrict__ x,
                             float* __restrict__ Hout) {
    __shared__ int nb[KNN];
    const int r = blockIdx.x, t = threadIdx.x;
    if (t < KNN) nb[t] = g_knn[r * KNN + t];
    __syncthreads();
    float s = 0.f;
#pragma unroll
    for (int i = 0; i < KNN; i++) s += Hin[(size_t)nb[i] * NF + t];
    Hout[(size_t)r * NF + t] = 0.03125f * s + 0.5f * x[(size_t)r * NF + t];
}

// ---------------- small dense layers ----------------
__global__ void linear_k(const float* __restrict__ In, int ldin,
                         const float* __restrict__ W, const float* __restrict__ b,
                         float* __restrict__ Out, int ldout, int coff,
                         int Kdim, int Ndim, int dorelu) {
    extern __shared__ float rs[];
    const int r = blockIdx.x, t = threadIdx.x;
    for (int k = t; k < Kdim; k += blockDim.x) rs[k] = In[(size_t)r * ldin + k];
    __syncthreads();
    float acc = b[t];
    for (int k = 0; k < Kdim; k++) acc = fmaf(rs[k], W[k * Ndim + t], acc);
    if (dorelu) acc = fmaxf(acc, 0.f);
    Out[(size_t)r * ldout + coff + t] = acc;
}

// ---------------- launch ---------------------------------------------------
extern "C" void kernel_launch(void* const* d_in, const int* in_sizes, int n_in,
                              void* d_out, int out_size) {
    (void)in_sizes; (void)n_in; (void)out_size;
    const float* x      = (const float*)d_in[0];
    const float* adj    = (const float*)d_in[1];
    const float* W_enc  = (const float*)d_in[2];
    const float* b_enc  = (const float*)d_in[3];
    const float* W_enc2 = (const float*)d_in[4];
    const float* b_enc2 = (const float*)d_in[5];
    const float* W_dec  = (const float*)d_in[6];
    const float* b_dec  = (const float*)d_in[7];

    float* out    = (float*)d_out;
    float* out_h1 = out;
    float* out_h2 = out + (size_t)NPTS * NH;
    float* out_G  = out + (size_t)2 * NPTS * NH;

    __half *adjh, *xh, *xl, *rh, *rl, *hh;
    float *h, *qa, *qb, *z, *res, *dist;
    cudaGetSymbolAddress((void**)&adjh, g_adjh);
    cudaGetSymbolAddress((void**)&xh,   g_xh);
    cudaGetSymbolAddress((void**)&xl,   g_xl);
    cudaGetSymbolAddress((void**)&rh,   g_rh);
    cudaGetSymbolAddress((void**)&rl,   g_rl);
    cudaGetSymbolAddress((void**)&hh,   g_hh);
    cudaGetSymbolAddress((void**)&h,    g_h);
    cudaGetSymbolAddress((void**)&qa,   g_qa);
    cudaGetSymbolAddress((void**)&qb,   g_qb);
    cudaGetSymbolAddress((void**)&z,    g_z);
    cudaGetSymbolAddress((void**)&res,  g_res);
    cudaGetSymbolAddress((void**)&dist, g_dist);

    const int HOP_SMEM = 3 * HBUF * 2;   // 107520 B
    cudaFuncSetAttribute(gemm3_tc, cudaFuncAttributeMaxDynamicSharedMemorySize, G3_SMEM);
    cudaFuncSetAttribute(hop_tc2,  cudaFuncAttributeMaxDynamicSharedMemorySize, HOP_SMEM);

    const dim3 gNT3(79, 157);            // 128-col x 64-row tiles
    const dim3 gHop(79, 4);

    // 1-3: conversions + norms
    split_adj_k<<<97657, 256>>>(adj, adjh, (size_t)NPTS * NPTS / 4);
    split_k<<<1250, 256>>>(x, xh, xl, (size_t)NPTS * NF / 4);
    rownorm_k<<<NPTS, NF>>>(x);
    // 4: distances (3-term split); 5: knn
    gemm3_tc<<<gNT3, 256, G3_SMEM>>>(xh, xl, xh, xl, dist, 0);
    topk_k<<<NPTS, 256>>>();

    // 6+: dense (adj) propagation, 5 hops
    hop_tc2<<<gHop, 256, HOP_SMEM>>>(adjh, xh, 128);
    combine_tc_k<<<5000, 256>>>(x);
    for (int i = 1; i < 5; i++) {
        hop_tc2<<<gHop, 256, HOP_SMEM>>>(adjh, hh, 128);
        combine_tc_k<<<5000, 256>>>(x);
    }

    // sparse (knn) propagation, 5 hops: x->qa->qb->qa->qb->qa
    sparse_hop_k<<<NPTS, NF>>>(x,  x, qa);
    sparse_hop_k<<<NPTS, NF>>>(qa, x, qb);
    sparse_hop_k<<<NPTS, NF>>>(qb, x, qa);
    sparse_hop_k<<<NPTS, NF>>>(qa, x, qb);
    sparse_hop_k<<<NPTS, NF>>>(qb, x, qa);

    // encoders -> h1, h2
    linear_k<<<NPTS, NH, NF * 4>>>(h,  NF, W_enc, b_enc, out_h1, NH, 0, NF, NH, 1);
    linear_k<<<NPTS, NH, NF * 4>>>(qa, NF, W_enc, b_enc, out_h2, NH, 0, NF, NH, 1);

    // encoder_2 -> z = [z1 | z2], decoder -> res
    linear_k<<<NPTS, NH, NH * 4>>>(out_h1, NH, W_enc2, b_enc2, z, NF, 0,  NH, NH, 1);
    linear_k<<<NPTS, NH, NH * 4>>>(out_h2, NH, W_enc2, b_enc2, z, NF, NH, NH, NH, 1);
    linear_k<<<NPTS, NF, NF * 4>>>(z, NF, W_dec, b_dec, res, NF, 0, NF, NF, 0);

    // res split + G = res @ res.T (3-term split)
    split_k<<<1250, 256>>>(res, rh, rl, (size_t)NPTS * NF / 4);
    gemm3_tc<<<gNT3, 256, G3_SMEM>>>(rh, rl, rh, rl, out_G, 1);
}